// round 16
// baseline (speedup 1.0000x reference)
#include <cuda_runtime.h>
#include <cstddef>

#define Bd  16
#define Ld  128
#define Rd  512
#define Fd  256
#define Hd  8
#define FHd 32
#define FEd 64
#define Ed  16384
#define HFd 256

// scratch for the expand branch (norm-linear outputs)
__device__ float g_xf[Bd * Ld * HFd];   // 2 MB
__device__ float g_yf[Bd * Rd * HFd];   // 8 MB
__device__ int   g_mask_mode;           // 0=u8, 1=i32, 2=f32, 3=bf16

__device__ __forceinline__ float lrelu(float x) { return x > 0.f ? x : 0.01f * x; }

// ---------------------------------------------------------------------------
// Probe: classify the mask buffer's element dtype from its first 4096 bytes.
// Values are 0/1 booleans (~90% true). Safe: min possible buffer = 256 KB.
// ---------------------------------------------------------------------------
__global__ void probe_mask_kernel(const unsigned char* __restrict__ m)
{
    if (threadIdx.x != 0 || blockIdx.x != 0) return;
    int n1 = 0, n3f = 0, inval = 0;
    for (int i = 0; i < 4096; i++) {
        unsigned char b = m[i];
        if (b == 1) n1++;
        if (b == 0x3F) n3f++;
        if (b > 1) inval++;
    }
    int mode;
    if (inval == 0) mode = (n1 > 2048) ? 0 : 1;   // plain bytes vs int32
    else            mode = (n3f > 1400) ? 3 : 2;  // bf16 vs float32
    g_mask_mode = mode;
}

__device__ __forceinline__ float read_mask(const void* m, long long idx, int mode)
{
    switch (mode) {
        case 0:  return ((const unsigned char*)m)[idx] ? 1.f : 0.f;
        case 1:  return ((const int*)m)[idx] ? 1.f : 0.f;
        case 2:  return (((const float*)m)[idx] != 0.f) ? 1.f : 0.f;
        default: return (((const unsigned short*)m)[idx] != 0) ? 1.f : 0.f;
    }
}

// ---------------------------------------------------------------------------
// Kernel 1: AttentionContract. One CTA per (b,l). 256 threads.
// GEMM (128 y-rows x 256 out, K=256) with fused attention-logit GEMV,
// layernorm, masked softmax over y, weighted contraction.
// ---------------------------------------------------------------------------
__global__ __launch_bounds__(256, 1)
void contract_kernel(const float* __restrict__ ll, const void* __restrict__ mask,
                     const float* __restrict__ Wc, const float* __restrict__ bc,
                     const float* __restrict__ gc, const float* __restrict__ bec,
                     const float* __restrict__ Wca, const float* __restrict__ bca,
                     float* __restrict__ out)
{
    extern __shared__ float sm[];
    float* A_s   = sm;                    // 32*129  (k-major, +1 pad)
    float* B_s   = A_s + 32 * 129;        // 256*33  (o-major, +1 pad)
    float* Wca_s = B_s + 256 * 33;        // 256*8   (k-major)
    float* atn_s = Wca_s + 256 * 8;       // 128*8
    float* red   = atn_s + 128 * 8;       // 16*256
    float* bc_s  = red + 16 * 256;        // 256
    float* gc_s  = bc_s + 256;            // 256
    float* bec_s = gc_s + 256;            // 256
    float* bca_s = bec_s + 256;           // 8
    float* msk_s = bca_s + 8;             // 128

    const int tid  = threadIdx.x;
    const int trow = tid >> 4;       // 0..15, owns rows trow*8 .. trow*8+7
    const int tcol = tid & 15;       // owns cols tcol + 16*c, c=0..15
    const int bl   = blockIdx.x;     // b*L + l
    const float* X = ll + (size_t)bl * (Ld * Fd);
    const int mmode = g_mask_mode;

    // constants
    bc_s[tid]  = bc[tid];
    gc_s[tid]  = gc[tid];
    bec_s[tid] = bec[tid];
    if (tid < 8)   bca_s[tid] = bca[tid];
    if (tid < 128) msk_s[tid] = read_mask(mask, (long long)bl * Ld + tid, mmode);
    for (int i = tid; i < 256 * 8; i += 256) {
        int k = i >> 3, h = i & 7;
        Wca_s[i] = Wca[h * Fd + k];
    }

    float acc[8][16];
    #pragma unroll
    for (int j = 0; j < 8; j++)
        #pragma unroll
        for (int c = 0; c < 16; c++) acc[j][c] = 0.f;
    float atn_acc[8];
    #pragma unroll
    for (int j = 0; j < 8; j++) atn_acc[j] = 0.f;

    const int hh = tcol & 7;
    const int r0 = trow * 8;

    for (int kt = 0; kt < 8; kt++) {
        const int k0 = kt * 32;
        __syncthreads();
        // A tile: rows 0..127, k-tile, leaky_relu applied. coalesced loads.
        for (int i = tid; i < 128 * 32; i += 256) {
            int y = i >> 5, k = i & 31;
            A_s[k * 129 + y] = lrelu(X[y * Fd + k0 + k]);
        }
        // B tile: Wc[o][k0+k]
        for (int i = tid; i < 256 * 32; i += 256) {
            int o = i >> 5, k = i & 31;
            B_s[o * 33 + k] = Wc[o * Fd + k0 + k];
        }
        __syncthreads();
        #pragma unroll
        for (int k = 0; k < 32; k++) {
            float a[8];
            #pragma unroll
            for (int j = 0; j < 8; j++) a[j] = A_s[k * 129 + r0 + j];
            float wv = Wca_s[(k0 + k) * 8 + hh];
            #pragma unroll
            for (int j = 0; j < 8; j++) atn_acc[j] += a[j] * wv;
            #pragma unroll
            for (int c = 0; c < 16; c++) {
                float bv = B_s[(tcol + 16 * c) * 33 + k];
                #pragma unroll
                for (int j = 0; j < 8; j++) acc[j][c] += a[j] * bv;
            }
        }
    }

    // bias + layernorm over the 256 output features (row-wise)
    float s1[8], s2[8];
    #pragma unroll
    for (int j = 0; j < 8; j++) { s1[j] = 0.f; s2[j] = 0.f; }
    #pragma unroll
    for (int c = 0; c < 16; c++) {
        int cg = tcol + 16 * c;
        float bv = bc_s[cg];
        #pragma unroll
        for (int j = 0; j < 8; j++) {
            float v = acc[j][c] + bv;
            acc[j][c] = v;
            s1[j] += v; s2[j] += v * v;
        }
    }
    #pragma unroll
    for (int m = 8; m >= 1; m >>= 1) {
        #pragma unroll
        for (int j = 0; j < 8; j++) {
            s1[j] += __shfl_xor_sync(0xffffffffu, s1[j], m);
            s2[j] += __shfl_xor_sync(0xffffffffu, s2[j], m);
        }
    }
    float mu[8], rs[8];
    #pragma unroll
    for (int j = 0; j < 8; j++) {
        mu[j] = s1[j] * (1.f / 256.f);
        float var = s2[j] * (1.f / 256.f) - mu[j] * mu[j];
        rs[j] = rsqrtf(var + 1e-5f);
    }
    #pragma unroll
    for (int c = 0; c < 16; c++) {
        int cg = tcol + 16 * c;
        float g = gc_s[cg], bt = bec_s[cg];
        #pragma unroll
        for (int j = 0; j < 8; j++)
            acc[j][c] = g * (acc[j][c] - mu[j]) * rs[j] + bt;
    }

    // attention logits -> smem (all tcol with same tcol&7 computed identical values)
    if (tcol < 8) {
        #pragma unroll
        for (int j = 0; j < 8; j++)
            atn_s[(r0 + j) * 8 + tcol] = atn_acc[j] + bca_s[tcol];
    }
    __syncthreads();

    // masked softmax over y per head; warp w handles head w
    {
        int w = tid >> 5, lane = tid & 31;
        float v[4];
        #pragma unroll
        for (int i = 0; i < 4; i++) v[i] = atn_s[(lane + 32 * i) * 8 + w];
        float m = fmaxf(fmaxf(v[0], v[1]), fmaxf(v[2], v[3]));
        #pragma unroll
        for (int s = 16; s >= 1; s >>= 1) m = fmaxf(m, __shfl_xor_sync(0xffffffffu, m, s));
        float e[4]; float ssum = 0.f;
        #pragma unroll
        for (int i = 0; i < 4; i++) { e[i] = msk_s[lane + 32 * i] * expf(v[i] - m); ssum += e[i]; }
        #pragma unroll
        for (int s = 16; s >= 1; s >>= 1) ssum += __shfl_xor_sync(0xffffffffu, ssum, s);
        float inv = 1.f / (ssum + 1e-10f);
        #pragma unroll
        for (int i = 0; i < 4; i++) atn_s[(lane + 32 * i) * 8 + w] = e[i] * inv;
    }
    __syncthreads();

    // contraction: sum over y of w[y, head(o)] * of[y, o]
    #pragma unroll
    for (int c = 0; c < 16; c++) {
        int cg = tcol + 16 * c;
        int hd = cg >> 5;
        float s = 0.f;
        #pragma unroll
        for (int j = 0; j < 8; j++) s += atn_s[(r0 + j) * 8 + hd] * acc[j][c];
        red[trow * 256 + cg] = s;
    }
    __syncthreads();
    {
        float s = 0.f;
        #pragma unroll
        for (int t = 0; t < 16; t++) s += red[t * 256 + tid];
        out[(size_t)bl * 256 + tid] = s;
    }
}

// ---------------------------------------------------------------------------
// Kernel 2a: generic NormAndLinear -> g_xf or g_yf. 32 rows per CTA.
// ---------------------------------------------------------------------------
__global__ __launch_bounds__(256)
void norm_linear_kernel(const float* __restrict__ X, const float* __restrict__ W,
                        const float* __restrict__ bb, const float* __restrict__ gg,
                        const float* __restrict__ beta, int dst)
{
    extern __shared__ float sm[];
    float* A_s  = sm;                 // 32*33
    float* B_s  = A_s + 32 * 33;      // 256*33
    float* b_s  = B_s + 256 * 33;     // 256
    float* g_s  = b_s + 256;          // 256
    float* be_s = g_s + 256;          // 256

    float* out = dst ? g_yf : g_xf;
    const int tid  = threadIdx.x;
    const int trow = tid >> 4;     // 0..15, owns rows trow*2, trow*2+1
    const int tcol = tid & 15;
    const float* Xr = X + (size_t)blockIdx.x * 32 * Fd;

    b_s[tid] = bb[tid]; g_s[tid] = gg[tid]; be_s[tid] = beta[tid];

    float acc[2][16];
    #pragma unroll
    for (int j = 0; j < 2; j++)
        #pragma unroll
        for (int c = 0; c < 16; c++) acc[j][c] = 0.f;
    const int r0 = trow * 2;

    for (int kt = 0; kt < 8; kt++) {
        const int k0 = kt * 32;
        __syncthreads();
        for (int i = tid; i < 32 * 32; i += 256) {
            int y = i >> 5, k = i & 31;
            A_s[k * 33 + y] = lrelu(Xr[y * Fd + k0 + k]);
        }
        for (int i = tid; i < 256 * 32; i += 256) {
            int o = i >> 5, k = i & 31;
            B_s[o * 33 + k] = W[o * Fd + k0 + k];
        }
        __syncthreads();
        #pragma unroll
        for (int k = 0; k < 32; k++) {
            float a0 = A_s[k * 33 + r0];
            float a1 = A_s[k * 33 + r0 + 1];
            #pragma unroll
            for (int c = 0; c < 16; c++) {
                float bv = B_s[(tcol + 16 * c) * 33 + k];
                acc[0][c] += a0 * bv;
                acc[1][c] += a1 * bv;
            }
        }
    }

    float s1[2] = {0.f, 0.f}, s2[2] = {0.f, 0.f};
    #pragma unroll
    for (int c = 0; c < 16; c++) {
        int cg = tcol + 16 * c;
        float bv = b_s[cg];
        #pragma unroll
        for (int j = 0; j < 2; j++) {
            float v = acc[j][c] + bv;
            acc[j][c] = v;
            s1[j] += v; s2[j] += v * v;
        }
    }
    #pragma unroll
    for (int m = 8; m >= 1; m >>= 1) {
        #pragma unroll
        for (int j = 0; j < 2; j++) {
            s1[j] += __shfl_xor_sync(0xffffffffu, s1[j], m);
            s2[j] += __shfl_xor_sync(0xffffffffu, s2[j], m);
        }
    }
    #pragma unroll
    for (int j = 0; j < 2; j++) {
        float mu = s1[j] * (1.f / 256.f);
        float rs = rsqrtf(s2[j] * (1.f / 256.f) - mu * mu + 1e-5f);
        size_t rowbase = ((size_t)blockIdx.x * 32 + r0 + j) * 256;
        #pragma unroll
        for (int c = 0; c < 16; c++) {
            int cg = tcol + 16 * c;
            out[rowbase + cg] = g_s[cg] * (acc[j][c] - mu) * rs + be_s[cg];
        }
    }
}

// ---------------------------------------------------------------------------
// Kernel 2b: expanded[b,x,y,h] = sum_f xf[b,x,h,f]*yf[b,y,h,f]
// CTA = (b, 32-x tile, 64-y tile)
// ---------------------------------------------------------------------------
__global__ __launch_bounds__(256)
void expand_kernel(float* __restrict__ out)
{
    extern __shared__ float sm[];
    float* X_s = sm;                 // 32 * 260 (pad for bank spread + f4 align)
    float* Y_s = X_s + 32 * 260;     // 64 * 260

    const int b  = blockIdx.x;
    const int xt = blockIdx.y;
    const int yt = blockIdx.z;
    const int tid = threadIdx.x;

    const float* Xg = g_xf + ((size_t)b * Ld + xt * 32) * HFd;
    const float* Yg = g_yf + ((size_t)b * Rd + yt * 64) * HFd;
    for (int i = tid; i < 32 * 256; i += 256) { int r = i >> 8, f = i & 255; X_s[r * 260 + f] = Xg[r * 256 + f]; }
    for (int i = tid; i < 64 * 256; i += 256) { int r = i >> 8, f = i & 255; Y_s[r * 260 + f] = Yg[r * 256 + f]; }
    __syncthreads();

    const int xl = tid >> 3;        // 0..31
    const int yg = tid & 7;         // y = yg + 8*i (strided -> conflict-free f4 reads)
    float acc[8][8];
    #pragma unroll
    for (int i = 0; i < 8; i++)
        #pragma unroll
        for (int h = 0; h < 8; h++) acc[i][h] = 0.f;

    #pragma unroll
    for (int h = 0; h < 8; h++) {
        #pragma unroll
        for (int f4 = 0; f4 < 8; f4++) {
            float4 x4 = *(const float4*)(X_s + xl * 260 + h * 32 + f4 * 4);
            #pragma unroll
            for (int i = 0; i < 8; i++) {
                float4 y4 = *(const float4*)(Y_s + (yg + 8 * i) * 260 + h * 32 + f4 * 4);
                acc[i][h] += x4.x * y4.x + x4.y * y4.y + x4.z * y4.z + x4.w * y4.w;
            }
        }
    }

    const int x = xt * 32 + xl;
    const size_t base = (((size_t)b * Ld + x) * Rd + yt * 64);
    #pragma unroll
    for (int i = 0; i < 8; i++) {
        int y = yg + 8 * i;
        float4 o0 = make_float4(acc[i][0], acc[i][1], acc[i][2], acc[i][3]);
        float4 o1 = make_float4(acc[i][4], acc[i][5], acc[i][6], acc[i][7]);
        float4* p = (float4*)(out + (base + y) * 8);
        p[0] = o0; p[1] = o1;
    }
}

// ---------------------------------------------------------------------------
// Kernel 3: edge gather -> linear(WeT in smem) -> lrelu -> atomic scatter-add
// CTA handles 128 edges in 8 chunks of 16. 128 CTAs total.
// ---------------------------------------------------------------------------
__global__ __launch_bounds__(256)
void edge_kernel(const float* __restrict__ lig,
                 const int* __restrict__ eb, const int* __restrict__ es, const int* __restrict__ ed,
                 const float* __restrict__ We, const float* __restrict__ be,
                 float* __restrict__ llf)
{
    extern __shared__ float sm[];
    float* WeT = sm;                  // 512 rows x 68 floats (row = k, 64 o + pad)
    float* x_s = WeT + 512 * 68;      // 16 * 512
    float* be_s = x_s + 16 * 512;     // 64

    const int tid = threadIdx.x;
    for (int i = tid; i < 64 * 512; i += 256) {
        int o = i >> 9, k = i & 511;
        WeT[k * 68 + o] = We[i];      // We row-major [o][k]
    }
    if (tid < 64) be_s[tid] = be[tid];

    const int e_base = blockIdx.x * 128;
    const int el = tid >> 4;          // 0..15 edge within chunk
    const int oq = tid & 15;          // output quad: o = 4*oq .. 4*oq+3

    for (int chunk = 0; chunk < 8; chunk++) {
        const int ce = e_base + chunk * 16;
        __syncthreads();
        // gather x = concat(lig[b,src], lig[b,dst])
        for (int i = tid; i < 16 * 512; i += 256) {
            int eL = i >> 9, k = i & 511;
            int e = ce + eL;
            int b = eb[e];
            int row = (k < 256) ? es[e] : ed[e];
            x_s[eL * 512 + k] = lig[((size_t)b * Ld + row) * Fd + (k & 255)];
        }
        __syncthreads();

        float4 acc = make_float4(0.f, 0.f, 0.f, 0.f);
        const float4* xr = (const float4*)(x_s + el * 512);
        #pragma unroll 4
        for (int k4 = 0; k4 < 128; k4++) {
            float4 x4 = xr[k4];
            const float4* w = (const float4*)(WeT + (k4 * 4) * 68) + oq;
            float4 w0 = w[0];
            float4 w1 = w[17];
            float4 w2 = w[34];
            float4 w3 = w[51];
            acc.x += x4.x * w0.x + x4.y * w1.x + x4.z * w2.x + x4.w * w3.x;
            acc.y += x4.x * w0.y + x4.y * w1.y + x4.z * w2.y + x4.w * w3.y;
            acc.z += x4.x * w0.z + x4.y * w1.z + x4.z * w2.z + x4.w * w3.z;
            acc.w += x4.x * w0.w + x4.y * w1.w + x4.z * w2.w + x4.w * w3.w;
        }
        const int e = ce + el;
        const int b = eb[e], s = es[e], d = ed[e];
        const size_t base = (((size_t)b * Ld + s) * Ld + d) * FEd + oq * 4;
        float v0 = lrelu(acc.x + be_s[oq * 4 + 0]);
        float v1 = lrelu(acc.y + be_s[oq * 4 + 1]);
        float v2 = lrelu(acc.z + be_s[oq * 4 + 2]);
        float v3 = lrelu(acc.w + be_s[oq * 4 + 3]);
        atomicAdd(llf + base + 0, v0);
        atomicAdd(llf + base + 1, v1);
        atomicAdd(llf + base + 2, v2);
        atomicAdd(llf + base + 3, v3);
    }
}

// ---------------------------------------------------------------------------
extern "C" void kernel_launch(void* const* d_in, const int* in_sizes, int n_in,
                              void* d_out, int out_size)
{
    (void)in_sizes; (void)n_in; (void)out_size;
    const float* ll   = (const float*)d_in[0];
    const float* lig  = (const float*)d_in[1];
    const float* rec  = (const float*)d_in[2];
    const void*  mask = d_in[3];
    const int* eb = (const int*)d_in[4];
    const int* es = (const int*)d_in[5];
    const int* ed = (const int*)d_in[6];
    const float* Wc  = (const float*)d_in[7];
    const float* bc  = (const float*)d_in[8];
    const float* gc  = (const float*)d_in[9];
    const float* bec = (const float*)d_in[10];
    const float* Wca = (const float*)d_in[11];
    const float* bca = (const float*)d_in[12];
    const float* Wex = (const float*)d_in[13];
    const float* bex = (const float*)d_in[14];
    const float* gex = (const float*)d_in[15];
    const float* beex= (const float*)d_in[16];
    const float* Wey = (const float*)d_in[17];
    const float* bey = (const float*)d_in[18];
    const float* gey = (const float*)d_in[19];
    const float* beey= (const float*)d_in[20];
    const float* We  = (const float*)d_in[21];
    const float* be  = (const float*)d_in[22];

    float* out   = (float*)d_out;
    float* out_c = out;                                          // (B,L,HF)
    float* out_e = out_c + (size_t)Bd * Ld * HFd;                // (B,L,R,H)
    float* out_l = out_e + (size_t)Bd * Ld * Rd * Hd;            // (B,L,L,FE)

    const int sm1 = 20648 * 4;   // contract
    const int sm2 = 10272 * 4;   // norm_linear
    const int sm3 = (32 * 260 + 64 * 260) * 4;  // expand
    const int sm4 = (512 * 68 + 16 * 512 + 64) * 4;  // edge

    cudaFuncSetAttribute((const void*)contract_kernel,    cudaFuncAttributeMaxDynamicSharedMemorySize, sm1);
    cudaFuncSetAttribute((const void*)norm_linear_kernel, cudaFuncAttributeMaxDynamicSharedMemorySize, sm2);
    cudaFuncSetAttribute((const void*)expand_kernel,      cudaFuncAttributeMaxDynamicSharedMemorySize, sm3);
    cudaFuncSetAttribute((const void*)edge_kernel,        cudaFuncAttributeMaxDynamicSharedMemorySize, sm4);

    // classify mask dtype (same stream -> ordered before contract in the graph)
    probe_mask_kernel<<<1, 32>>>((const unsigned char*)mask);

    // zero the scatter target (d_out is poisoned)
    cudaMemsetAsync(out_l, 0, (size_t)Bd * Ld * Ld * FEd * sizeof(float), 0);

    // expand branch
    norm_linear_kernel<<<(Bd * Ld) / 32, 256, sm2>>>(lig, Wex, bex, gex, beex, 0);
    norm_linear_kernel<<<(Bd * Rd) / 32, 256, sm2>>>(rec, Wey, bey, gey, beey, 1);
    dim3 ge(Bd, Ld / 32, Rd / 64);
    expand_kernel<<<ge, 256, sm3>>>(out_e);

    edge_kernel<<<Ed / 128, 256, sm4>>>(lig, eb, es, ed, We, be, out_l);

    contract_kernel<<<Bd * Ld, 256, sm1>>>(ll, mask, Wc, bc, gc, bec, Wca, bca, out_c);
}

// round 17
// speedup vs baseline: 1.4399x; 1.4399x over previous
#include <cuda_runtime.h>
#include <cstdint>
#include <cstddef>

#define Bd  16
#define Ld  128
#define Rd  512
#define Fd  256
#define Hd  8
#define FHd 32
#define FEd 64
#define Ed  16384
#define HFd 256

// scratch for the expand branch (norm-linear outputs)
__device__ float g_xf[Bd * Ld * HFd];   // 2 MB
__device__ float g_yf[Bd * Rd * HFd];   // 8 MB
__device__ int   g_mask_mode;           // 0=u8, 1=i32, 2=f32, 3=bf16

__device__ __forceinline__ float lrelu(float x) { return x > 0.f ? x : 0.01f * x; }

__device__ __forceinline__ uint32_t f2tf32(float x) {
    uint32_t r;
    asm("cvt.rna.tf32.f32 %0, %1;" : "=r"(r) : "f"(x));
    return r;
}

__device__ __forceinline__ void mma_tf32(float* c,
                                         uint32_t a0, uint32_t a1, uint32_t a2, uint32_t a3,
                                         uint32_t b0, uint32_t b1)
{
    asm volatile(
        "mma.sync.aligned.m16n8k8.row.col.f32.tf32.tf32.f32 "
        "{%0,%1,%2,%3}, {%4,%5,%6,%7}, {%8,%9}, {%0,%1,%2,%3};"
        : "+f"(c[0]), "+f"(c[1]), "+f"(c[2]), "+f"(c[3])
        : "r"(a0), "r"(a1), "r"(a2), "r"(a3), "r"(b0), "r"(b1));
}

// ---------------------------------------------------------------------------
// Probe: classify the mask buffer's element dtype from its first 4096 bytes.
// ---------------------------------------------------------------------------
__global__ void probe_mask_kernel(const unsigned char* __restrict__ m)
{
    if (threadIdx.x != 0 || blockIdx.x != 0) return;
    int n1 = 0, n3f = 0, inval = 0;
    for (int i = 0; i < 4096; i++) {
        unsigned char b = m[i];
        if (b == 1) n1++;
        if (b == 0x3F) n3f++;
        if (b > 1) inval++;
    }
    int mode;
    if (inval == 0) mode = (n1 > 2048) ? 0 : 1;   // plain bytes vs int32
    else            mode = (n3f > 1400) ? 3 : 2;  // bf16 vs float32
    g_mask_mode = mode;
}

__device__ __forceinline__ float read_mask(const void* m, long long idx, int mode)
{
    switch (mode) {
        case 0:  return ((const unsigned char*)m)[idx] ? 1.f : 0.f;
        case 1:  return ((const int*)m)[idx] ? 1.f : 0.f;
        case 2:  return (((const float*)m)[idx] != 0.f) ? 1.f : 0.f;
        default: return (((const unsigned short*)m)[idx] != 0) ? 1.f : 0.f;
    }
}

// ---------------------------------------------------------------------------
// Kernel 1: AttentionContract via tf32 tensor-core MMA.
// One CTA per (b,l). 256 threads = 8 warps. Warp w owns output cols
// [32w, 32w+32) for all 128 rows, plus the attention-logit tile rows
// [16w, 16w+16) x 8 heads. K tiled by 64 (4 tiles).
// ---------------------------------------------------------------------------
__global__ __launch_bounds__(256, 1)
void contract_mma_kernel(const float* __restrict__ ll, const void* __restrict__ mask,
                         const float* __restrict__ Wc, const float* __restrict__ bc,
                         const float* __restrict__ gc, const float* __restrict__ bec,
                         const float* __restrict__ Wca, const float* __restrict__ bca,
                         float* __restrict__ out)
{
    extern __shared__ float smf[];
    uint32_t* A_s = (uint32_t*)smf;           // 128 x 68 (tf32, row-major, pad 4)
    uint32_t* B_s = A_s + 128 * 68;           // 264 x 68 (cols 0..255 = Wc, 256..263 = Wca)
    float* atn_s = (float*)(B_s + 264 * 68);  // 128 x 8 logits -> softmax weights (in place)
    float* s1_s  = atn_s + 1024;              // 128 x 8 per-warp row sums
    float* s2_s  = s1_s + 1024;               // 128 x 8 per-warp row sq-sums
    float* mu_s  = s2_s + 1024;               // 128
    float* rs_s  = mu_s + 128;                // 128
    float* bc_s  = rs_s + 128;                // 256
    float* gc_s  = bc_s + 256;                // 256
    float* bec_s = gc_s + 256;                // 256
    float* bca_s = bec_s + 256;               // 8
    float* msk_s = bca_s + 8;                 // 128

    const int tid  = threadIdx.x;
    const int w    = tid >> 5;        // warp 0..7
    const int lane = tid & 31;
    const int q    = lane >> 2;       // 0..7 : fragment row group
    const int m    = lane & 3;        // 0..3 : fragment k / col pair
    const int bl   = blockIdx.x;
    const float* X = ll + (size_t)bl * (Ld * Fd);
    const int mmode = g_mask_mode;

    bc_s[tid]  = bc[tid];
    gc_s[tid]  = gc[tid];
    bec_s[tid] = bec[tid];
    if (tid < 8)   bca_s[tid] = bca[tid];
    if (tid < 128) msk_s[tid] = read_mask(mask, (long long)bl * Ld + tid, mmode);

    float c[8][4][4];                 // [row-tile][n-tile][frag reg]
    #pragma unroll
    for (int rt = 0; rt < 8; rt++)
        #pragma unroll
        for (int nt = 0; nt < 4; nt++)
            #pragma unroll
            for (int r = 0; r < 4; r++) c[rt][nt][r] = 0.f;
    float ce[4] = {0.f, 0.f, 0.f, 0.f};   // attention-logit tile (rows 16w.., heads)

    for (int kt = 0; kt < 4; kt++) {
        const int k0 = kt * 64;
        __syncthreads();
        // A tile: lrelu + tf32 convert, 128x64
        #pragma unroll 4
        for (int i = tid; i < 128 * 64; i += 256) {
            int y = i >> 6, k = i & 63;
            A_s[y * 68 + k] = f2tf32(lrelu(X[y * Fd + k0 + k]));
        }
        // B tile: Wc 256x64
        #pragma unroll 4
        for (int i = tid; i < 256 * 64; i += 256) {
            int o = i >> 6, k = i & 63;
            B_s[o * 68 + k] = f2tf32(Wc[o * Fd + k0 + k]);
        }
        // Wca as extra cols 256..263
        for (int i = tid; i < 8 * 64; i += 256) {
            int h = i >> 6, k = i & 63;
            B_s[(256 + h) * 68 + k] = f2tf32(Wca[h * Fd + k0 + k]);
        }
        __syncthreads();

        #pragma unroll
        for (int k8 = 0; k8 < 8; k8++) {
            const int kb = k8 * 8;
            uint32_t b0[4], b1[4];
            #pragma unroll
            for (int nt = 0; nt < 4; nt++) {
                int o = w * 32 + nt * 8 + q;
                b0[nt] = B_s[o * 68 + kb + m];
                b1[nt] = B_s[o * 68 + kb + 4 + m];
            }
            uint32_t wb0 = B_s[(256 + q) * 68 + kb + m];
            uint32_t wb1 = B_s[(256 + q) * 68 + kb + 4 + m];

            #pragma unroll
            for (int rt = 0; rt < 8; rt++) {
                int y = rt * 16 + q;
                uint32_t a0 = A_s[y * 68 + kb + m];
                uint32_t a1 = A_s[(y + 8) * 68 + kb + m];
                uint32_t a2 = A_s[y * 68 + kb + 4 + m];
                uint32_t a3 = A_s[(y + 8) * 68 + kb + 4 + m];
                #pragma unroll
                for (int nt = 0; nt < 4; nt++)
                    mma_tf32(c[rt][nt], a0, a1, a2, a3, b0[nt], b1[nt]);
                if (rt == w)
                    mma_tf32(ce, a0, a1, a2, a3, wb0, wb1);
            }
        }
    }

    // --- attention logits (rows 16w.., head = 2m+ci) ---
    {
        int rl = 16 * w + q;
        atn_s[rl * 8 + 2 * m]           = ce[0] + bca_s[2 * m];
        atn_s[rl * 8 + 2 * m + 1]       = ce[1] + bca_s[2 * m + 1];
        atn_s[(rl + 8) * 8 + 2 * m]     = ce[2] + bca_s[2 * m];
        atn_s[(rl + 8) * 8 + 2 * m + 1] = ce[3] + bca_s[2 * m + 1];
    }

    // --- add bias, per-warp LN partials ---
    #pragma unroll
    for (int rt = 0; rt < 8; rt++) {
        float slo = 0.f, qlo = 0.f, shi = 0.f, qhi = 0.f;
        #pragma unroll
        for (int nt = 0; nt < 4; nt++) {
            int col0 = w * 32 + nt * 8 + 2 * m;
            float bv0 = bc_s[col0], bv1 = bc_s[col0 + 1];
            float v0 = c[rt][nt][0] + bv0; c[rt][nt][0] = v0; slo += v0; qlo += v0 * v0;
            float v1 = c[rt][nt][1] + bv1; c[rt][nt][1] = v1; slo += v1; qlo += v1 * v1;
            float v2 = c[rt][nt][2] + bv0; c[rt][nt][2] = v2; shi += v2; qhi += v2 * v2;
            float v3 = c[rt][nt][3] + bv1; c[rt][nt][3] = v3; shi += v3; qhi += v3 * v3;
        }
        // reduce across the 4 lanes (m) sharing a row
        #pragma unroll
        for (int s = 1; s <= 2; s <<= 1) {
            slo += __shfl_xor_sync(0xffffffffu, slo, s);
            qlo += __shfl_xor_sync(0xffffffffu, qlo, s);
            shi += __shfl_xor_sync(0xffffffffu, shi, s);
            qhi += __shfl_xor_sync(0xffffffffu, qhi, s);
        }
        if (m == 0) {
            int rl = rt * 16 + q;
            s1_s[rl * 8 + w] = slo;  s2_s[rl * 8 + w] = qlo;
            s1_s[(rl + 8) * 8 + w] = shi;  s2_s[(rl + 8) * 8 + w] = qhi;
        }
    }
    __syncthreads();

    // --- masked softmax over y, head w per warp (weights back into atn_s) ---
    {
        float v[4];
        #pragma unroll
        for (int i = 0; i < 4; i++) v[i] = atn_s[(lane + 32 * i) * 8 + w];
        float mx = fmaxf(fmaxf(v[0], v[1]), fmaxf(v[2], v[3]));
        #pragma unroll
        for (int s = 16; s >= 1; s >>= 1) mx = fmaxf(mx, __shfl_xor_sync(0xffffffffu, mx, s));
        float e[4]; float ssum = 0.f;
        #pragma unroll
        for (int i = 0; i < 4; i++) { e[i] = msk_s[lane + 32 * i] * expf(v[i] - mx); ssum += e[i]; }
        #pragma unroll
        for (int s = 16; s >= 1; s >>= 1) ssum += __shfl_xor_sync(0xffffffffu, ssum, s);
        float inv = 1.f / (ssum + 1e-10f);
        #pragma unroll
        for (int i = 0; i < 4; i++) atn_s[(lane + 32 * i) * 8 + w] = e[i] * inv;
    }
    // --- row LN stats (threads 0..127) ---
    if (tid < 128) {
        float s1 = 0.f, s2 = 0.f;
        #pragma unroll
        for (int j = 0; j < 8; j++) { s1 += s1_s[tid * 8 + j]; s2 += s2_s[tid * 8 + j]; }
        float mu = s1 * (1.f / 256.f);
        float var = s2 * (1.f / 256.f) - mu * mu;
        mu_s[tid] = mu;
        rs_s[tid] = rsqrtf(var + 1e-5f);
    }
    __syncthreads();

    // --- normalize + weighted contraction over rows ---
    float acc2[4][2];
    #pragma unroll
    for (int nt = 0; nt < 4; nt++) { acc2[nt][0] = 0.f; acc2[nt][1] = 0.f; }

    #pragma unroll
    for (int rt = 0; rt < 8; rt++) {
        int rl = rt * 16 + q, rh = rl + 8;
        float mul = mu_s[rl], rsl = rs_s[rl];
        float muh = mu_s[rh], rsh = rs_s[rh];
        float plo = atn_s[rl * 8 + w];
        float phi = atn_s[rh * 8 + w];
        #pragma unroll
        for (int nt = 0; nt < 4; nt++) {
            int col0 = w * 32 + nt * 8 + 2 * m;
            float g0 = gc_s[col0], g1 = gc_s[col0 + 1];
            float t0 = bec_s[col0], t1 = bec_s[col0 + 1];
            float v0 = g0 * (c[rt][nt][0] - mul) * rsl + t0;
            float v1 = g1 * (c[rt][nt][1] - mul) * rsl + t1;
            float v2 = g0 * (c[rt][nt][2] - muh) * rsh + t0;
            float v3 = g1 * (c[rt][nt][3] - muh) * rsh + t1;
            acc2[nt][0] += plo * v0 + phi * v2;
            acc2[nt][1] += plo * v1 + phi * v3;
        }
    }
    // reduce over q (lanes stride 4)
    #pragma unroll
    for (int s = 4; s <= 16; s <<= 1) {
        #pragma unroll
        for (int nt = 0; nt < 4; nt++) {
            acc2[nt][0] += __shfl_xor_sync(0xffffffffu, acc2[nt][0], s);
            acc2[nt][1] += __shfl_xor_sync(0xffffffffu, acc2[nt][1], s);
        }
    }
    if (lane < 4) {
        #pragma unroll
        for (int nt = 0; nt < 4; nt++) {
            int col = w * 32 + nt * 8 + 2 * lane;
            out[(size_t)bl * 256 + col]     = acc2[nt][0];
            out[(size_t)bl * 256 + col + 1] = acc2[nt][1];
        }
    }
}

// ---------------------------------------------------------------------------
// Kernel 2a: generic NormAndLinear -> g_xf or g_yf. 32 rows per CTA.
// ---------------------------------------------------------------------------
__global__ __launch_bounds__(256)
void norm_linear_kernel(const float* __restrict__ X, const float* __restrict__ W,
                        const float* __restrict__ bb, const float* __restrict__ gg,
                        const float* __restrict__ beta, int dst)
{
    extern __shared__ float sm[];
    float* A_s  = sm;                 // 32*33
    float* B_s  = A_s + 32 * 33;      // 256*33
    float* b_s  = B_s + 256 * 33;     // 256
    float* g_s  = b_s + 256;          // 256
    float* be_s = g_s + 256;          // 256

    float* out = dst ? g_yf : g_xf;
    const int tid  = threadIdx.x;
    const int trow = tid >> 4;
    const int tcol = tid & 15;
    const float* Xr = X + (size_t)blockIdx.x * 32 * Fd;

    b_s[tid] = bb[tid]; g_s[tid] = gg[tid]; be_s[tid] = beta[tid];

    float acc[2][16];
    #pragma unroll
    for (int j = 0; j < 2; j++)
        #pragma unroll
        for (int c = 0; c < 16; c++) acc[j][c] = 0.f;
    const int r0 = trow * 2;

    for (int kt = 0; kt < 8; kt++) {
        const int k0 = kt * 32;
        __syncthreads();
        for (int i = tid; i < 32 * 32; i += 256) {
            int y = i >> 5, k = i & 31;
            A_s[k * 33 + y] = lrelu(Xr[y * Fd + k0 + k]);
        }
        for (int i = tid; i < 256 * 32; i += 256) {
            int o = i >> 5, k = i & 31;
            B_s[o * 33 + k] = W[o * Fd + k0 + k];
        }
        __syncthreads();
        #pragma unroll
        for (int k = 0; k < 32; k++) {
            float a0 = A_s[k * 33 + r0];
            float a1 = A_s[k * 33 + r0 + 1];
            #pragma unroll
            for (int c = 0; c < 16; c++) {
                float bv = B_s[(tcol + 16 * c) * 33 + k];
                acc[0][c] += a0 * bv;
                acc[1][c] += a1 * bv;
            }
        }
    }

    float s1[2] = {0.f, 0.f}, s2[2] = {0.f, 0.f};
    #pragma unroll
    for (int c = 0; c < 16; c++) {
        int cg = tcol + 16 * c;
        float bv = b_s[cg];
        #pragma unroll
        for (int j = 0; j < 2; j++) {
            float v = acc[j][c] + bv;
            acc[j][c] = v;
            s1[j] += v; s2[j] += v * v;
        }
    }
    #pragma unroll
    for (int mS = 8; mS >= 1; mS >>= 1) {
        #pragma unroll
        for (int j = 0; j < 2; j++) {
            s1[j] += __shfl_xor_sync(0xffffffffu, s1[j], mS);
            s2[j] += __shfl_xor_sync(0xffffffffu, s2[j], mS);
        }
    }
    #pragma unroll
    for (int j = 0; j < 2; j++) {
        float mu = s1[j] * (1.f / 256.f);
        float rs = rsqrtf(s2[j] * (1.f / 256.f) - mu * mu + 1e-5f);
        size_t rowbase = ((size_t)blockIdx.x * 32 + r0 + j) * 256;
        #pragma unroll
        for (int c = 0; c < 16; c++) {
            int cg = tcol + 16 * c;
            out[rowbase + cg] = g_s[cg] * (acc[j][c] - mu) * rs + be_s[cg];
        }
    }
}

// ---------------------------------------------------------------------------
// Kernel 2b: expanded[b,x,y,h] = sum_f xf[b,x,h,f]*yf[b,y,h,f]
// ---------------------------------------------------------------------------
__global__ __launch_bounds__(256)
void expand_kernel(float* __restrict__ out)
{
    extern __shared__ float sm[];
    float* X_s = sm;                 // 32 * 260
    float* Y_s = X_s + 32 * 260;     // 64 * 260

    const int b  = blockIdx.x;
    const int xt = blockIdx.y;
    const int yt = blockIdx.z;
    const int tid = threadIdx.x;

    const float* Xg = g_xf + ((size_t)b * Ld + xt * 32) * HFd;
    const float* Yg = g_yf + ((size_t)b * Rd + yt * 64) * HFd;
    for (int i = tid; i < 32 * 256; i += 256) { int r = i >> 8, f = i & 255; X_s[r * 260 + f] = Xg[r * 256 + f]; }
    for (int i = tid; i < 64 * 256; i += 256) { int r = i >> 8, f = i & 255; Y_s[r * 260 + f] = Yg[r * 256 + f]; }
    __syncthreads();

    const int xl = tid >> 3;
    const int yg = tid & 7;
    float acc[8][8];
    #pragma unroll
    for (int i = 0; i < 8; i++)
        #pragma unroll
        for (int h = 0; h < 8; h++) acc[i][h] = 0.f;

    #pragma unroll
    for (int h = 0; h < 8; h++) {
        #pragma unroll
        for (int f4 = 0; f4 < 8; f4++) {
            float4 x4 = *(const float4*)(X_s + xl * 260 + h * 32 + f4 * 4);
            #pragma unroll
            for (int i = 0; i < 8; i++) {
                float4 y4 = *(const float4*)(Y_s + (yg + 8 * i) * 260 + h * 32 + f4 * 4);
                acc[i][h] += x4.x * y4.x + x4.y * y4.y + x4.z * y4.z + x4.w * y4.w;
            }
        }
    }

    const int x = xt * 32 + xl;
    const size_t base = (((size_t)b * Ld + x) * Rd + yt * 64);
    #pragma unroll
    for (int i = 0; i < 8; i++) {
        int y = yg + 8 * i;
        float4 o0 = make_float4(acc[i][0], acc[i][1], acc[i][2], acc[i][3]);
        float4 o1 = make_float4(acc[i][4], acc[i][5], acc[i][6], acc[i][7]);
        float4* p = (float4*)(out + (base + y) * 8);
        p[0] = o0; p[1] = o1;
    }
}

// ---------------------------------------------------------------------------
// Kernel 3: edge gather -> linear -> lrelu -> atomic scatter-add
// ---------------------------------------------------------------------------
__global__ __launch_bounds__(256)
void edge_kernel(const float* __restrict__ lig,
                 const int* __restrict__ eb, const int* __restrict__ es, const int* __restrict__ ed,
                 const float* __restrict__ We, const float* __restrict__ be,
                 float* __restrict__ llf)
{
    extern __shared__ float sm[];
    float* WeT = sm;                  // 512 x 68
    float* x_s = WeT + 512 * 68;      // 16 * 512
    float* be_s = x_s + 16 * 512;     // 64

    const int tid = threadIdx.x;
    for (int i = tid; i < 64 * 512; i += 256) {
        int o = i >> 9, k = i & 511;
        WeT[k * 68 + o] = We[i];
    }
    if (tid < 64) be_s[tid] = be[tid];

    const int e_base = blockIdx.x * 128;
    const int el = tid >> 4;
    const int oq = tid & 15;

    for (int chunk = 0; chunk < 8; chunk++) {
        const int ce = e_base + chunk * 16;
        __syncthreads();
        for (int i = tid; i < 16 * 512; i += 256) {
            int eL = i >> 9, k = i & 511;
            int e = ce + eL;
            int b = eb[e];
            int row = (k < 256) ? es[e] : ed[e];
            x_s[eL * 512 + k] = lig[((size_t)b * Ld + row) * Fd + (k & 255)];
        }
        __syncthreads();

        float4 acc = make_float4(0.f, 0.f, 0.f, 0.f);
        const float4* xr = (const float4*)(x_s + el * 512);
        #pragma unroll 4
        for (int k4 = 0; k4 < 128; k4++) {
            float4 x4 = xr[k4];
            const float4* wp = (const float4*)(WeT + (k4 * 4) * 68) + oq;
            float4 w0 = wp[0];
            float4 w1 = wp[17];
            float4 w2 = wp[34];
            float4 w3 = wp[51];
            acc.x += x4.x * w0.x + x4.y * w1.x + x4.z * w2.x + x4.w * w3.x;
            acc.y += x4.x * w0.y + x4.y * w1.y + x4.z * w2.y + x4.w * w3.y;
            acc.z += x4.x * w0.z + x4.y * w1.z + x4.z * w2.z + x4.w * w3.z;
            acc.w += x4.x * w0.w + x4.y * w1.w + x4.z * w2.w + x4.w * w3.w;
        }
        const int e = ce + el;
        const int b = eb[e], s = es[e], d = ed[e];
        const size_t base = (((size_t)b * Ld + s) * Ld + d) * FEd + oq * 4;
        atomicAdd(llf + base + 0, lrelu(acc.x + be_s[oq * 4 + 0]));
        atomicAdd(llf + base + 1, lrelu(acc.y + be_s[oq * 4 + 1]));
        atomicAdd(llf + base + 2, lrelu(acc.z + be_s[oq * 4 + 2]));
        atomicAdd(llf + base + 3, lrelu(acc.w + be_s[oq * 4 + 3]));
    }
}

// ---------------------------------------------------------------------------
extern "C" void kernel_launch(void* const* d_in, const int* in_sizes, int n_in,
                              void* d_out, int out_size)
{
    (void)in_sizes; (void)n_in; (void)out_size;
    const float* ll   = (const float*)d_in[0];
    const float* lig  = (const float*)d_in[1];
    const float* rec  = (const float*)d_in[2];
    const void*  mask = d_in[3];
    const int* eb = (const int*)d_in[4];
    const int* es = (const int*)d_in[5];
    const int* ed = (const int*)d_in[6];
    const float* Wc  = (const float*)d_in[7];
    const float* bc  = (const float*)d_in[8];
    const float* gc  = (const float*)d_in[9];
    const float* bec = (const float*)d_in[10];
    const float* Wca = (const float*)d_in[11];
    const float* bca = (const float*)d_in[12];
    const float* Wex = (const float*)d_in[13];
    const float* bex = (const float*)d_in[14];
    const float* gex = (const float*)d_in[15];
    const float* beex= (const float*)d_in[16];
    const float* Wey = (const float*)d_in[17];
    const float* bey = (const float*)d_in[18];
    const float* gey = (const float*)d_in[19];
    const float* beey= (const float*)d_in[20];
    const float* We  = (const float*)d_in[21];
    const float* be  = (const float*)d_in[22];

    float* out   = (float*)d_out;
    float* out_c = out;                                          // (B,L,HF)
    float* out_e = out_c + (size_t)Bd * Ld * HFd;                // (B,L,R,H)
    float* out_l = out_e + (size_t)Bd * Ld * Rd * Hd;            // (B,L,L,FE)

    const int sm1 = 123552;                          // contract_mma
    const int sm2 = 10272 * 4;                       // norm_linear
    const int sm3 = (32 * 260 + 64 * 260) * 4;       // expand
    const int sm4 = (512 * 68 + 16 * 512 + 64) * 4;  // edge

    cudaFuncSetAttribute((const void*)contract_mma_kernel, cudaFuncAttributeMaxDynamicSharedMemorySize, sm1);
    cudaFuncSetAttribute((const void*)norm_linear_kernel,  cudaFuncAttributeMaxDynamicSharedMemorySize, sm2);
    cudaFuncSetAttribute((const void*)expand_kernel,       cudaFuncAttributeMaxDynamicSharedMemorySize, sm3);
    cudaFuncSetAttribute((const void*)edge_kernel,         cudaFuncAttributeMaxDynamicSharedMemorySize, sm4);

    // classify mask dtype (ordered before contract on the same stream)
    probe_mask_kernel<<<1, 32>>>((const unsigned char*)mask);

    // zero the scatter target (d_out is poisoned)
    cudaMemsetAsync(out_l, 0, (size_t)Bd * Ld * Ld * FEd * sizeof(float), 0);

    // expand branch
    norm_linear_kernel<<<(Bd * Ld) / 32, 256, sm2>>>(lig, Wex, bex, gex, beex, 0);
    norm_linear_kernel<<<(Bd * Rd) / 32, 256, sm2>>>(rec, Wey, bey, gey, beey, 1);
    dim3 ge(Bd, Ld / 32, Rd / 64);
    expand_kernel<<<ge, 256, sm3>>>(out_e);

    edge_kernel<<<Ed / 128, 256, sm4>>>(lig, eb, es, ed, We, be, out_l);

    contract_mma_kernel<<<Bd * Ld, 256, sm1>>>(ll, mask, Wc, bc, gc, bec, Wca, bca, out_c);
}